// round 12
// baseline (speedup 1.0000x reference)
#include <cuda_runtime.h>
#include <cuda_bf16.h>
#include <cstdint>

// Problem constants
#define T_DIM   64
#define NCH     2048
#define KDIM    65536
#define THRESHV 16384.0f
#define KWTA    16

// GEMM config: 16 n-blocks x SPLITK 18 = 288 CTAs (<= 2 per SM, balanced)
#define SPLITK  18
#define BK      16

// fp32 staging ring: 4 stages x (A 64x16 fp32 = 4KB, B 128x16 fp32 = 8KB)
#define FPSTG   12288
#define FP_B    4096
// bf16 ring: 3 stages x 18432 (AH 0, AL 3072, BH 6144, BL 12288; 48B row stride)
#define BFBASE  49152
#define BFSTG   18432
#define RSTRIDE 48
#define AH_OFF  0
#define AL_OFF  3072
#define BH_OFF  6144
#define BL_OFF  12288
#define SMEM_TOTAL (BFBASE + 3 * BFSTG)   // 104448

#define POSTBLK 64   // fused_post grid size (all resident)

// Static scratch (no allocations allowed)
__device__ float g_partial[SPLITK][T_DIM * NCH];   // 9.4 MB
__device__ int   g_cnt[NCH];
__device__ float g_fp[NCH];
__device__ unsigned int g_tickets = 0;   // monotonic grid-sync counter

// ---------------------------------------------------------------------------
// Helpers
// ---------------------------------------------------------------------------
__device__ __forceinline__ uint32_t smem_u32(const void* p) {
    uint32_t a;
    asm("{ .reg .u64 t; cvta.to.shared.u64 t, %1; cvt.u32.u64 %0, t; }"
        : "=r"(a) : "l"(p));
    return a;
}
__device__ __forceinline__ void cp16(uint32_t dst, const void* src) {
    asm volatile("cp.async.cg.shared.global [%0], [%1], 16;"
                 :: "r"(dst), "l"(src) : "memory");
}
#define CP_COMMIT() asm volatile("cp.async.commit_group;" ::: "memory")
#define CP_WAIT(n)  asm volatile("cp.async.wait_group %0;" :: "n"(n) : "memory")

// Split float2 -> hi bf16x2 (RN) + lo bf16x2 (residual). Proven exact R3-R11.
__device__ __forceinline__ void split2(float x, float y, uint32_t& h, uint32_t& l) {
    asm("cvt.rn.bf16x2.f32 %0, %1, %2;" : "=r"(h) : "f"(y), "f"(x));
    float hx = __uint_as_float(h << 16);
    float hy = __uint_as_float(h & 0xFFFF0000u);
    float lx = x - hx;
    float ly = y - hy;
    asm("cvt.rn.bf16x2.f32 %0, %1, %2;" : "=r"(l) : "f"(ly), "f"(lx));
}

__device__ __forceinline__ void mma16816(float* c, const uint32_t* a,
                                         uint32_t b0, uint32_t b1) {
    asm volatile(
        "mma.sync.aligned.m16n8k16.row.col.f32.bf16.bf16.f32 "
        "{%0,%1,%2,%3}, {%4,%5,%6,%7}, {%8,%9}, {%0,%1,%2,%3};"
        : "+f"(c[0]), "+f"(c[1]), "+f"(c[2]), "+f"(c[3])
        : "r"(a[0]), "r"(a[1]), "r"(a[2]), "r"(a[3]), "r"(b0), "r"(b1));
}

__device__ __forceinline__ void ldsm4(uint32_t* r, uint32_t addr) {
    asm volatile("ldmatrix.sync.aligned.m8n8.x4.shared.b16 {%0,%1,%2,%3}, [%4];"
                 : "=r"(r[0]), "=r"(r[1]), "=r"(r[2]), "=r"(r[3]) : "r"(addr));
}

__device__ __forceinline__ void cvt_sts(const char* fp, char* hiP, char* loP) {
    float4 v = *(const float4*)fp;
    uint32_t h0, l0, h1, l1;
    split2(v.x, v.y, h0, l0);
    split2(v.z, v.w, h1, l1);
    *(uint2*)hiP = make_uint2(h0, h1);
    *(uint2*)loP = make_uint2(l0, l1);
}

// (val, idx) comparator: higher val wins, tie -> lower idx. Matches lax.top_k.
__device__ __forceinline__ void cmb(float& bv, int& bi, float ov, int oi) {
    if (ov > bv || (ov == bv && oi < bi)) { bv = ov; bi = oi; }
}

// ---------------------------------------------------------------------------
// Kernel 1: bf16 HMMA split-K GEMM (byte-identical structure to R8-R11).
// ---------------------------------------------------------------------------
__global__ void __launch_bounds__(256, 2)
gemm_mma(const float* __restrict__ rec, const float* __restrict__ w) {
    extern __shared__ char sm[];
    const uint32_t sbase = smem_u32(sm);

    const int tid  = threadIdx.x;
    const int wid  = tid >> 5;
    const int lane = tid & 31;
    const int g    = lane >> 2;
    const int q    = lane & 3;
    const int wm   = wid >> 2;
    const int wn   = wid & 3;
    const int nblk = blockIdx.x * 128;
    const int s    = blockIdx.y;
    const int nit  = (s < 10) ? 228 : 227;
    const int ch0  = (s < 10) ? s * 228 : 2280 + (s - 10) * 227;
    const size_t k0 = (size_t)ch0 * BK;

    const int lr  = tid >> 2;
    const int lkc = (tid & 3) * 4;
    const float* aS  = rec + (size_t)lr * KDIM + k0 + lkc;
    const float* bS0 = w + (size_t)(nblk + lr) * KDIM + k0 + lkc;
    const float* bS1 = bS0 + (size_t)64 * KDIM;
    const uint32_t fpA = (uint32_t)lr * 64 + lkc * 4;
    const uint32_t fpB = FP_B + (uint32_t)lr * 64 + lkc * 4;
    const uint32_t bfO = (uint32_t)lr * RSTRIDE + lkc * 2;

    const int j  = lane >> 3;
    const int l7 = lane & 7;
    const uint32_t aOff = (uint32_t)(wm * 32 + (j & 1) * 8 + l7) * RSTRIDE
                        + (j >> 1) * 16 + AH_OFF;
    const uint32_t bOff = (uint32_t)(wn * 32 + (j >> 1) * 8 + l7) * RSTRIDE
                        + (j & 1) * 16 + BH_OFF;

    float acc[2][4][4];
    #pragma unroll
    for (int m = 0; m < 2; m++)
        #pragma unroll
        for (int n = 0; n < 4; n++)
            #pragma unroll
            for (int i = 0; i < 4; i++) acc[m][n][i] = 0.0f;

    #pragma unroll
    for (int st = 0; st < 3; st++) {
        const uint32_t fo = sbase + st * FPSTG;
        const int co = st * BK;
        cp16(fo + fpA, aS + co);
        cp16(fo + fpB, bS0 + co);
        cp16(fo + fpB + 4096, bS1 + co);
        CP_COMMIT();
    }
    CP_WAIT(2);
    {
        const char* fs = sm;
        char* bs = sm + BFBASE;
        cvt_sts(fs + fpA, bs + AH_OFF + bfO, bs + AL_OFF + bfO);
        cvt_sts(fs + fpB, bs + BH_OFF + bfO, bs + BL_OFF + bfO);
        cvt_sts(fs + fpB + 4096, bs + BH_OFF + 3072 + bfO, bs + BL_OFF + 3072 + bfO);
    }

    int bfc = 0;

    #pragma unroll 1
    for (int it = 0; it < nit; it++) {
        const int nc = it + 3;
        if (nc < nit) {
            const uint32_t fo = sbase + (nc & 3) * FPSTG;
            const int co = nc * BK;
            cp16(fo + fpA, aS + co);
            cp16(fo + fpB, bS0 + co);
            cp16(fo + fpB + 4096, bS1 + co);
        }
        CP_COMMIT();
        CP_WAIT(2);
        __syncthreads();

        const int bfn = (bfc == 2) ? 0 : bfc + 1;
        if (it + 1 < nit) {
            const char* fs = sm + ((it + 1) & 3) * FPSTG;
            char* bs = sm + BFBASE + bfn * BFSTG;
            cvt_sts(fs + fpA, bs + AH_OFF + bfO, bs + AL_OFF + bfO);
            cvt_sts(fs + fpB, bs + BH_OFF + bfO, bs + BL_OFF + bfO);
            cvt_sts(fs + fpB + 4096, bs + BH_OFF + 3072 + bfO,
                    bs + BL_OFF + 3072 + bfO);
        }

        const uint32_t sb = sbase + BFBASE + bfc * BFSTG;
        uint32_t Ah0[4], Ah1[4], Al0[4], Al1[4];
        ldsm4(Ah0, sb + aOff);
        ldsm4(Ah1, sb + aOff + 16 * RSTRIDE);
        ldsm4(Al0, sb + aOff + (AL_OFF - AH_OFF));
        ldsm4(Al1, sb + aOff + (AL_OFF - AH_OFF) + 16 * RSTRIDE);
        uint32_t Bh0[4], Bh1[4], Bl0[4], Bl1[4];
        ldsm4(Bh0, sb + bOff);
        ldsm4(Bh1, sb + bOff + 16 * RSTRIDE);
        ldsm4(Bl0, sb + bOff + (BL_OFF - BH_OFF));
        ldsm4(Bl1, sb + bOff + (BL_OFF - BH_OFF) + 16 * RSTRIDE);

        const uint32_t* Bh[4] = { &Bh0[0], &Bh0[2], &Bh1[0], &Bh1[2] };
        const uint32_t* Bl[4] = { &Bl0[0], &Bl0[2], &Bl1[0], &Bl1[2] };
        const uint32_t* Ah[2] = { Ah0, Ah1 };
        const uint32_t* Al[2] = { Al0, Al1 };

        #pragma unroll
        for (int m = 0; m < 2; m++) {
            #pragma unroll
            for (int n = 0; n < 4; n++) {
                mma16816(acc[m][n], Ah[m], Bh[n][0], Bh[n][1]);
                mma16816(acc[m][n], Ah[m], Bl[n][0], Bl[n][1]);
                mma16816(acc[m][n], Al[m], Bh[n][0], Bh[n][1]);
            }
        }
        bfc = bfn;
    }

    float* gp = g_partial[s];
    const int t0 = wm * 32;
    #pragma unroll
    for (int m = 0; m < 2; m++) {
        const int r0 = t0 + m * 16 + g;
        #pragma unroll
        for (int n = 0; n < 4; n++) {
            const int cb = nblk + wn * 32 + n * 8 + 2 * q;
            *(float2*)&gp[r0 * NCH + cb]       = make_float2(acc[m][n][0], acc[m][n][1]);
            *(float2*)&gp[(r0 + 8) * NCH + cb] = make_float2(acc[m][n][2], acc[m][n][3]);
        }
    }
}

// ---------------------------------------------------------------------------
// Kernel 2: fused post-processing. 64 blocks x 1024 threads, one grid sync.
// Block b owns columns [b*32, b*32+32). Thread <-> (t, col-pair):
//   cp = tid & 15 (pair of columns), t = tid >> 4 (0..63).
// Phase 1 loads are float2 (halved LDG count vs R11), fully coalesced.
// ---------------------------------------------------------------------------
__global__ void __launch_bounds__(1024)
fused_post(float* __restrict__ out) {
    __shared__ float pot_s[T_DIM][32];      // [t][c] 8 KB
    __shared__ int   cs[T_DIM][16];         // packed (cnt0 | cnt1<<16), 4 KB
    __shared__ float tot_s[NCH];            // 8 KB
    __shared__ float coef_s[NCH];           // 8 KB
    __shared__ float wv[32];
    __shared__ int   wi[32];
    __shared__ float bc_v;
    __shared__ unsigned int tgt_s;

    const int tid  = threadIdx.x;
    const int lane = tid & 31;
    const int wid  = tid >> 5;
    const int cp   = tid & 15;              // column pair within block
    const int t    = tid >> 4;              // 0..63
    const int col0 = blockIdx.x * 32 + cp * 2;

    // ---- Phase 1: reduce partials -> pot tile (one float2 per thread) ----
    {
        const int idx = t * NCH + col0;     // 8B-aligned
        float s0 = 0.0f, s1 = 0.0f;
        #pragma unroll
        for (int p = 0; p < SPLITK; p++) {
            const float2 v = *(const float2*)&g_partial[p][idx];
            s0 += v.x;
            s1 += v.y;
        }
        pot_s[t][cp * 2]     = s0;
        pot_s[t][cp * 2 + 1] = s1;
        cs[t][cp] = (s0 > THRESHV ? 1 : 0) | ((s1 > THRESHV ? 1 : 0) << 16);
    }
    __syncthreads();

    // Count reduce over t (packed tree in smem; 1024 -> 16 active lanes)
    #pragma unroll
    for (int st = 32; st > 0; st >>= 1) {
        if (tid < st * 16) cs[t][cp] += cs[t + st][cp];
        __syncthreads();
    }

    if (tid < 32) {
        const int c = tid;                   // column within block
        const int kcol = blockIdx.x * 32 + c;
        const int packed = cs[0][c >> 1];
        const int total = (c & 1) ? (packed >> 16) : (packed & 0xFFFF);
        int fi = T_DIM - total;
        if (fi > T_DIM - 1) fi = T_DIM - 1;
        if (fi < 0) fi = 0;
        float o = pot_s[fi][c];
        g_cnt[kcol] = total;
        g_fp[kcol]  = (o > THRESHV) ? o : 0.0f;
    }

    // ---- Grid sync (ticket barrier, monotonic across graph replays) ----
    __threadfence();
    __syncthreads();
    if (tid == 0) {
        unsigned int ticket = atomicAdd(&g_tickets, 1u);
        tgt_s = (ticket / (unsigned)POSTBLK + 1u) * (unsigned)POSTBLK;
    }
    __syncthreads();
    if (tid == 0) {
        volatile unsigned int* vc = &g_tickets;
        while (*vc < tgt_s) { }
    }
    __syncthreads();
    __threadfence();

    // ---- Phase 2: winners (redundant per block; shfl comparator R10/R11) ----
    const int k0 = tid, k1 = tid + 1024;
    const int cn0 = g_cnt[k0], cn1 = g_cnt[k1];
    const float fp0 = g_fp[k0], fp1 = g_fp[k1];

    float m = fmaxf((cn0 > 0) ? fp0 : 0.0f, (cn1 > 0) ? fp1 : 0.0f);
    #pragma unroll
    for (int o = 16; o > 0; o >>= 1)
        m = fmaxf(m, __shfl_down_sync(0xFFFFFFFFu, m, o));
    if (lane == 0) wv[wid] = m;
    __syncthreads();
    if (wid == 0) {
        float mm = wv[lane];
        #pragma unroll
        for (int o = 16; o > 0; o >>= 1)
            mm = fmaxf(mm, __shfl_down_sync(0xFFFFFFFFu, mm, o));
        if (lane == 0) bc_v = mm * (float)T_DIM;
    }
    __syncthreads();
    const float v = bc_v;

    {
        const float t0 = fp0 + v;
        float s0 = 0.0f;
        for (int i = 0; i < cn0; i++) s0 += t0;
        tot_s[k0] = s0;
        const float t1 = fp1 + v;
        float s1 = 0.0f;
        for (int i = 0; i < cn1; i++) s1 += t1;
        tot_s[k1] = s1;
        coef_s[k0] = 0.0f;
        coef_s[k1] = 0.0f;
    }
    __syncthreads();

    for (int it = 0; it < KWTA; it++) {
        float bv = tot_s[k0];
        int   bi = k0;
        cmb(bv, bi, tot_s[k1], k1);
        #pragma unroll
        for (int o = 16; o > 0; o >>= 1) {
            float ov = __shfl_down_sync(0xFFFFFFFFu, bv, o);
            int   oi = __shfl_down_sync(0xFFFFFFFFu, bi, o);
            cmb(bv, bi, ov, oi);
        }
        if (lane == 0) { wv[wid] = bv; wi[wid] = bi; }
        __syncthreads();
        if (wid == 0) {
            float fv = wv[lane];
            int   fi = wi[lane];
            #pragma unroll
            for (int o = 16; o > 0; o >>= 1) {
                float ov = __shfl_down_sync(0xFFFFFFFFu, fv, o);
                int   oi = __shfl_down_sync(0xFFFFFFFFu, fi, o);
                cmb(fv, fi, ov, oi);
            }
            if (lane == 0) {
                if (fv > 0.0f) coef_s[fi] = 1.0f;
                tot_s[fi] = -3.4e38f;
            }
        }
        __syncthreads();
    }

    // ---- Phase 3: output from smem pot tile (float2 stores) ----
    {
        const float cf0 = coef_s[col0];
        const float cf1 = coef_s[col0 + 1];
        float2 o2;
        o2.x = (pot_s[t][cp * 2]     > THRESHV && cf0 > 0.0f) ? 1.0f : 0.0f;
        o2.y = (pot_s[t][cp * 2 + 1] > THRESHV && cf1 > 0.0f) ? 1.0f : 0.0f;
        *(float2*)&out[t * NCH + col0] = o2;
    }
}

// ---------------------------------------------------------------------------
extern "C" void kernel_launch(void* const* d_in, const int* in_sizes, int n_in,
                              void* d_out, int out_size) {
    const float* rec = (const float*)d_in[0];   // (64, 1, 256, 256)
    const float* w   = (const float*)d_in[1];   // (2048, 1, 256, 256)
    float* out = (float*)d_out;                 // (64, 2048, 1, 1) float32

    cudaFuncSetAttribute(gemm_mma, cudaFuncAttributeMaxDynamicSharedMemorySize,
                         SMEM_TOTAL);
    dim3 grid(NCH / 128, SPLITK);               // (16, 18) = 288 CTAs, <=2/SM
    gemm_mma<<<grid, 256, SMEM_TOTAL>>>(rec, w);
    fused_post<<<POSTBLK, 1024>>>(out);
}